// round 8
// baseline (speedup 1.0000x reference)
#include <cuda_runtime.h>
#include <cstdint>

// EdgeUpdate via mma.sync.m16n8k8.tf32, 512 threads / 16 warps, pipelined gather.
// Tile = 128 edges x 128 outs. Warp (mi,nj): 32-edge x 32-out band, 2x4 mma tiles.
// GEMM1: K=256 in 8 chunks of 32k, ping-pong smem buffers, LDG prefetch 1 chunk ahead.
// GEMM2: K=128 in 2 rounds of 64k, h1 exchanged through smem.
#define THREADS 512
#define NTILES  5000           // 640000 / 128
#define PXS     132            // uint2 row stride, GEMM1 pair buffer
#define CHUNK_U2 (16 * PXS)    // uint2 per chunk buffer
#define HSTRIDE 136            // float row stride, GEMM2 h1 buffer

// smem byte offsets
#define OW1 0                  // uint2 [128 pr][128 n] : 131072 B
#define OW2 131072             // uint2 [ 64 pr][128 n] :  65536 B
#define OX  196608             // chunk bufs (2x16896) / h1 (34816) / red (4096)
#define SMEM_BYTES (OX + 64 * HSTRIDE * 4)   // 231424

__device__ __forceinline__ unsigned tf32r(float x) {
  unsigned r; asm("cvt.rna.tf32.f32 %0, %1;" : "=r"(r) : "f"(x)); return r;
}
__device__ __forceinline__ float silu_f(float x) {
  return x * (1.0f / (1.0f + __expf(-x)));
}
__device__ __forceinline__ void mma8(float* d, unsigned a0, unsigned a1,
                                     unsigned a2, unsigned a3,
                                     unsigned b0, unsigned b1) {
  asm volatile("mma.sync.aligned.m16n8k8.row.col.f32.tf32.tf32.f32 "
    "{%0,%1,%2,%3}, {%4,%5,%6,%7}, {%8,%9}, {%0,%1,%2,%3};"
    : "+f"(d[0]), "+f"(d[1]), "+f"(d[2]), "+f"(d[3])
    : "r"(a0), "r"(a1), "r"(a2), "r"(a3), "r"(b0), "r"(b1));
}

__global__ void __launch_bounds__(THREADS, 1)
edge_update_mma3(const float* __restrict__ nodes,
                 const float* __restrict__ efeat,
                 const int*   __restrict__ srcI,
                 const int*   __restrict__ dstI,
                 const float* __restrict__ W1,
                 const float* __restrict__ b1,
                 const float* __restrict__ W2,
                 const float* __restrict__ b2,
                 const float* __restrict__ gamma,
                 const float* __restrict__ beta,
                 float* __restrict__ out)
{
  extern __shared__ char smem[];
  uint2* w1p = (uint2*)(smem + OW1);
  uint2* w2p = (uint2*)(smem + OW2);
  uint2* pxu = (uint2*)(smem + OX);          // GEMM1 pair chunk buffers
  unsigned* sxu = (unsigned*)(smem + OX);    // GEMM2 unpacked h1 buffer

  const int tid  = threadIdx.x;
  const int warp = tid >> 5, lane = tid & 31;
  const int kl = lane & 3, r = lane >> 2;
  const int mi = warp >> 2;            // edges [32*mi, 32*mi+32)
  const int nj = warp & 3;             // outs  [32*nj, 32*nj+32)
  const int mbase = mi * 32;
  const int nbase = nj * 32;

  // ---- stage weights as (k, k+4) tf32 pairs, swizzled n ^ ((pr&3)<<2) ----
  for (int i = tid; i < 16384; i += THREADS) {
    int pr = i >> 7, n = i & 127;
    int k0 = (pr >> 2) * 8 + (pr & 3);
    w1p[pr * 128 + (n ^ ((pr & 3) << 2))] =
        make_uint2(tf32r(W1[k0 * 128 + n]), tf32r(W1[(k0 + 4) * 128 + n]));
  }
  for (int i = tid; i < 8192; i += THREADS) {
    int pr = i >> 7, n = i & 127;
    int k0 = (pr >> 2) * 8 + (pr & 3);
    w2p[pr * 128 + (n ^ ((pr & 3) << 2))] =
        make_uint2(tf32r(W2[k0 * 128 + n]), tf32r(W2[(k0 + 4) * 128 + n]));
  }
  __syncthreads();

  const int ee = tid & 127, part = tid >> 7;   // fill mapping: edge, k8-group

  for (int tile = blockIdx.x; tile < NTILES; tile += gridDim.x) {
    const int e0 = tile * 128;
    const size_t si = (size_t)srcI[e0 + ee] * 64;
    const size_t di = (size_t)dstI[e0 + ee] * 64;
    const float* efrow = efeat + (size_t)(e0 + ee) * 128;
    __syncthreads();   // previous tile's epilogue smem reads complete

    float d1[2][4][4];
#pragma unroll
    for (int t = 0; t < 2; t++)
#pragma unroll
      for (int u = 0; u < 4; u++)
#pragma unroll
        for (int j = 0; j < 4; j++) d1[t][u][j] = 0.f;

    // prefetch chunk 0 (src node, k 0..31; this thread's 8-k slice)
    float4 v0, v1;
    {
      const float4* b4 = (const float4*)(nodes + si + part * 8);
      v0 = b4[0]; v1 = b4[1];
    }

    // ================= GEMM1: 8 chunks of 32k =================
#pragma unroll
    for (int c = 0; c < 8; c++) {
      // store chunk c (raw fp32 bits; HMMA reads tf32 subset)
      uint2* pb = pxu + (c & 1) * CHUNK_U2;
      pb[(part * 4 + 0) * PXS + ee] = make_uint2(__float_as_uint(v0.x), __float_as_uint(v1.x));
      pb[(part * 4 + 1) * PXS + ee] = make_uint2(__float_as_uint(v0.y), __float_as_uint(v1.y));
      pb[(part * 4 + 2) * PXS + ee] = make_uint2(__float_as_uint(v0.z), __float_as_uint(v1.z));
      pb[(part * 4 + 3) * PXS + ee] = make_uint2(__float_as_uint(v0.w), __float_as_uint(v1.w));
      __syncthreads();

      // prefetch chunk c+1 (latency hidden behind compute below)
      if (c < 7) {
        const int cn = c + 1;
        const float* bp = (cn < 2) ? nodes + si + cn * 32
                        : (cn < 4) ? nodes + di + (cn - 2) * 32
                                   : efrow + (cn - 4) * 32;
        const float4* b4 = (const float4*)(bp + part * 8);
        v0 = b4[0]; v1 = b4[1];
      }

      // compute chunk c
      const uint2* pc = pxu + (c & 1) * CHUNK_U2;
      const int prc = c * 16;
#pragma unroll
      for (int k8 = 0; k8 < 4; k8++) {
        const int prb = k8 * 4 + kl;
        uint2 a0[2], a1[2], bb[4];
#pragma unroll
        for (int t = 0; t < 2; t++) {
          int m = mbase + t * 16 + r;
          a0[t] = pc[prb * PXS + m];
          a1[t] = pc[prb * PXS + m + 8];
        }
#pragma unroll
        for (int u = 0; u < 4; u++) {
          int n = nbase + u * 8 + r;
          bb[u] = w1p[(prc + prb) * 128 + (n ^ (kl << 2))];
        }
#pragma unroll
        for (int t = 0; t < 2; t++)
#pragma unroll
          for (int u = 0; u < 4; u++)
            mma8(d1[t][u], a0[t].x, a1[t].x, a0[t].y, a1[t].y, bb[u].x, bb[u].y);
      }
    }

    // ---- h1 = silu(D1 + b1), raw fp32 bits ----
    unsigned h1f[2][4][4];
#pragma unroll
    for (int t = 0; t < 2; t++)
#pragma unroll
      for (int u = 0; u < 4; u++) {
        int n = nbase + u * 8 + 2 * kl;
        float ba = __ldg(&b1[n]), bbv = __ldg(&b1[n + 1]);
        h1f[t][u][0] = __float_as_uint(silu_f(d1[t][u][0] + ba));
        h1f[t][u][1] = __float_as_uint(silu_f(d1[t][u][1] + bbv));
        h1f[t][u][2] = __float_as_uint(silu_f(d1[t][u][2] + ba));
        h1f[t][u][3] = __float_as_uint(silu_f(d1[t][u][3] + bbv));
      }

    float d2[2][4][4];
#pragma unroll
    for (int t = 0; t < 2; t++)
#pragma unroll
      for (int u = 0; u < 4; u++)
#pragma unroll
        for (int j = 0; j < 4; j++) d2[t][u][j] = 0.f;

    __syncthreads();   // GEMM1 buffer reads done before h1 overwrites region

    // ================= GEMM2: 2 rounds of 64k =================
#pragma unroll
    for (int c2 = 0; c2 < 2; c2++) {
      if ((nj >> 1) == c2) {
        const int kloc0 = (nj & 1) * 32;
#pragma unroll
        for (int t = 0; t < 2; t++)
#pragma unroll
          for (int u = 0; u < 4; u++) {
            int m = mbase + t * 16 + r;
            int kk = kloc0 + u * 8 + 2 * kl;
            sxu[kk * HSTRIDE + m]           = h1f[t][u][0];
            sxu[(kk + 1) * HSTRIDE + m]     = h1f[t][u][1];
            sxu[kk * HSTRIDE + m + 8]       = h1f[t][u][2];
            sxu[(kk + 1) * HSTRIDE + m + 8] = h1f[t][u][3];
          }
      }
      __syncthreads();

      const int prc = c2 * 32;
#pragma unroll
      for (int k8 = 0; k8 < 8; k8++) {
        const int kb = k8 * 8;
        unsigned a[2][4];
        uint2 bb[4];
#pragma unroll
        for (int t = 0; t < 2; t++) {
          int m = mbase + t * 16 + r;
          a[t][0] = sxu[(kb + kl) * HSTRIDE + m];
          a[t][1] = sxu[(kb + kl) * HSTRIDE + m + 8];
          a[t][2] = sxu[(kb + 4 + kl) * HSTRIDE + m];
          a[t][3] = sxu[(kb + 4 + kl) * HSTRIDE + m + 8];
        }
#pragma unroll
        for (int u = 0; u < 4; u++) {
          int n = nbase + u * 8 + r;
          bb[u] = w2p[(prc + k8 * 4 + kl) * 128 + (n ^ (kl << 2))];
        }
#pragma unroll
        for (int t = 0; t < 2; t++)
#pragma unroll
          for (int u = 0; u < 4; u++)
            mma8(d2[t][u], a[t][0], a[t][1], a[t][2], a[t][3], bb[u].x, bb[u].y);
      }
      __syncthreads();
    }

    // ================= epilogue: y = efeat + silu(D2+b2); LN =================
    float y[2][4][4];
    float s0[2], q0[2], s1[2], q1[2];
#pragma unroll
    for (int t = 0; t < 2; t++) { s0[t] = q0[t] = s1[t] = q1[t] = 0.f; }
#pragma unroll
    for (int t = 0; t < 2; t++) {
      int m = mbase + t * 16 + r;
#pragma unroll
      for (int u = 0; u < 4; u++) {
        int n = nbase + u * 8 + 2 * kl;
        float ba = __ldg(&b2[n]), bbv = __ldg(&b2[n + 1]);
        float2 ef0 = *(const float2*)(efeat + (size_t)(e0 + m) * 128 + n);
        float2 ef1 = *(const float2*)(efeat + (size_t)(e0 + m + 8) * 128 + n);
        float v0_ = ef0.x + silu_f(d2[t][u][0] + ba);
        float v1_ = ef0.y + silu_f(d2[t][u][1] + bbv);
        float v2_ = ef1.x + silu_f(d2[t][u][2] + ba);
        float v3_ = ef1.y + silu_f(d2[t][u][3] + bbv);
        y[t][u][0] = v0_; y[t][u][1] = v1_; y[t][u][2] = v2_; y[t][u][3] = v3_;
        s0[t] += v0_ + v1_; q0[t] += v0_ * v0_ + v1_ * v1_;
        s1[t] += v2_ + v3_; q1[t] += v2_ * v2_ + v3_ * v3_;
      }
    }
#pragma unroll
    for (int t = 0; t < 2; t++) {
#pragma unroll
      for (int off = 1; off <= 2; off <<= 1) {
        s0[t] += __shfl_xor_sync(0xffffffffu, s0[t], off);
        q0[t] += __shfl_xor_sync(0xffffffffu, q0[t], off);
        s1[t] += __shfl_xor_sync(0xffffffffu, s1[t], off);
        q1[t] += __shfl_xor_sync(0xffffffffu, q1[t], off);
      }
    }
    // cross-warp-quadrant LN combine through smem (region free after last bar)
    float2* red = (float2*)sxu;   // [4 nj][128 m]
    if (kl == 0) {
#pragma unroll
      for (int t = 0; t < 2; t++) {
        int m = mbase + t * 16 + r;
        red[nj * 128 + m]     = make_float2(s0[t], q0[t]);
        red[nj * 128 + m + 8] = make_float2(s1[t], q1[t]);
      }
    }
    __syncthreads();
#pragma unroll
    for (int t = 0; t < 2; t++) {
      int m = mbase + t * 16 + r;
      float S0 = 0.f, Q0 = 0.f, S1 = 0.f, Q1 = 0.f;
#pragma unroll
      for (int qd = 0; qd < 4; qd++) {
        float2 v = red[qd * 128 + m];     S0 += v.x; Q0 += v.y;
        float2 w = red[qd * 128 + m + 8]; S1 += w.x; Q1 += w.y;
      }
      float mean0 = S0 * 0.0078125f;
      float var0  = Q0 * 0.0078125f - mean0 * mean0;
      float rs0   = rsqrtf(var0 + 1e-5f);
      float mean1 = S1 * 0.0078125f;
      float var1  = Q1 * 0.0078125f - mean1 * mean1;
      float rs1   = rsqrtf(var1 + 1e-5f);
#pragma unroll
      for (int u = 0; u < 4; u++) {
        int n = nbase + u * 8 + 2 * kl;
        float g0 = __ldg(&gamma[n]), g1 = __ldg(&gamma[n + 1]);
        float t0 = __ldg(&beta[n]),  t1 = __ldg(&beta[n + 1]);
        float2 o0, o1;
        o0.x = (y[t][u][0] - mean0) * rs0 * g0 + t0;
        o0.y = (y[t][u][1] - mean0) * rs0 * g1 + t1;
        o1.x = (y[t][u][2] - mean1) * rs1 * g0 + t0;
        o1.y = (y[t][u][3] - mean1) * rs1 * g1 + t1;
        *(float2*)(out + (size_t)(e0 + m) * 128 + n)     = o0;
        *(float2*)(out + (size_t)(e0 + m + 8) * 128 + n) = o1;
      }
    }
    // next tile's top-of-loop __syncthreads orders red reuse
  }
}

extern "C" void kernel_launch(void* const* d_in, const int* in_sizes, int n_in,
                              void* d_out, int out_size) {
  const float* nodes = (const float*)d_in[0];
  const float* efeat = (const float*)d_in[1];
  const int*   srcI  = (const int*)d_in[2];
  const int*   dstI  = (const int*)d_in[3];
  const float* W1    = (const float*)d_in[4];
  const float* b1    = (const float*)d_in[5];
  const float* W2    = (const float*)d_in[6];
  const float* b2    = (const float*)d_in[7];
  const float* gamma = (const float*)d_in[8];
  const float* beta  = (const float*)d_in[9];
  float* out = (float*)d_out;

  cudaFuncSetAttribute(edge_update_mma3,
                       cudaFuncAttributeMaxDynamicSharedMemorySize, SMEM_BYTES);
  int sms = 148;
  cudaDeviceGetAttribute(&sms, cudaDevAttrMultiProcessorCount, 0);
  if (sms < 1) sms = 148;

  edge_update_mma3<<<sms, THREADS, SMEM_BYTES>>>(
      nodes, efeat, srcI, dstI, W1, b1, W2, b2, gamma, beta, out);
}

// round 9
// speedup vs baseline: 1.3090x; 1.3090x over previous
#include <cuda_runtime.h>
#include <cstdint>

// EdgeUpdate via mma.sync.m16n8k8.tf32, 512 threads / 16 warps.
// R7 structure (64k chunks, 2 barriers/chunk) + register diet + no activation cvt.
#define THREADS 512
#define NTILES  5000          // 640000 / 128
#define PXS     132           // pair-row stride in float2 units (132 mod 16 = 4)
#define HSTRIDE 136           // unpacked h1 stride (floats)

// smem byte offsets
#define OW1 0                 // uint2 [128 pr][128 n]  : 131072 B
#define OW2 131072            // uint2 [ 64 pr][128 n]  :  65536 B
#define OX  196608            // px pairs (33792 B) / h1 unpacked (34816 B) / red
#define SMEM_BYTES (196608 + 64 * HSTRIDE * 4)   // 231424

__device__ __forceinline__ unsigned tf32r(float x) {
  unsigned r; asm("cvt.rna.tf32.f32 %0, %1;" : "=r"(r) : "f"(x)); return r;
}
__device__ __forceinline__ float silu_f(float x) {
  return x * (1.0f / (1.0f + __expf(-x)));
}
__device__ __forceinline__ void mma8(float* d, unsigned a0, unsigned a1,
                                     unsigned a2, unsigned a3,
                                     unsigned b0, unsigned b1) {
  asm volatile("mma.sync.aligned.m16n8k8.row.col.f32.tf32.tf32.f32 "
    "{%0,%1,%2,%3}, {%4,%5,%6,%7}, {%8,%9}, {%0,%1,%2,%3};"
    : "+f"(d[0]), "+f"(d[1]), "+f"(d[2]), "+f"(d[3])
    : "r"(a0), "r"(a1), "r"(a2), "r"(a3), "r"(b0), "r"(b1));
}

__global__ void __launch_bounds__(THREADS, 1)
edge_update_mma4(const float* __restrict__ nodes,
                 const float* __restrict__ efeat,
                 const int*   __restrict__ srcI,
                 const int*   __restrict__ dstI,
                 const float* __restrict__ W1,
                 const float* __restrict__ b1,
                 const float* __restrict__ W2,
                 const float* __restrict__ b2,
                 const float* __restrict__ gamma,
                 const float* __restrict__ beta,
                 float* __restrict__ out)
{
  extern __shared__ char smem[];
  uint2* w1p = (uint2*)(smem + OW1);
  uint2* w2p = (uint2*)(smem + OW2);
  uint2* pxu = (uint2*)(smem + OX);          // [32 pr][PXS] pairs
  unsigned* sxu = (unsigned*)(smem + OX);    // [64 k][HSTRIDE] unpacked h1

  const int tid  = threadIdx.x;
  const int warp = tid >> 5, lane = tid & 31;
  const int kl = lane & 3, r = lane >> 2;
  const int mi = warp >> 2;            // edges [32*mi, 32*mi+32)
  const int nj = warp & 3;             // outs  [32*nj, 32*nj+32)
  const int mbase = mi * 32;
  const int nbase = nj * 32;

  // ---- stage weights as (k, k+4) tf32 pairs, swizzled n ^ ((pr&3)<<2) ----
  for (int i = tid; i < 16384; i += THREADS) {
    int pr = i >> 7, n = i & 127;
    int k0 = (pr >> 2) * 8 + (pr & 3);
    w1p[pr * 128 + (n ^ ((pr & 3) << 2))] =
        make_uint2(tf32r(W1[k0 * 128 + n]), tf32r(W1[(k0 + 4) * 128 + n]));
  }
  for (int i = tid; i < 8192; i += THREADS) {
    int pr = i >> 7, n = i & 127;
    int k0 = (pr >> 2) * 8 + (pr & 3);
    w2p[pr * 128 + (n ^ ((pr & 3) << 2))] =
        make_uint2(tf32r(W2[k0 * 128 + n]), tf32r(W2[(k0 + 4) * 128 + n]));
  }
  __syncthreads();

  for (int tile = blockIdx.x; tile < NTILES; tile += gridDim.x) {
    const int e0 = tile * 128;

    // ================= GEMM1: D1 = X[128,256] @ W1 =================
    float d1[2][4][4];
#pragma unroll
    for (int t = 0; t < 2; t++)
#pragma unroll
      for (int u = 0; u < 4; u++)
#pragma unroll
        for (int j = 0; j < 4; j++) d1[t][u][j] = 0.f;

#pragma unroll 1
    for (int c = 0; c < 4; c++) {
      __syncthreads();   // previous px use complete
      // gather 64-k chunk c -> px pairs [32 pr][e] (raw fp32 bits)
      {
        const int e = tid & 127, q4 = tid >> 7;   // q4: 0..3, two k8-groups each
        const float* base;
        if (c == 0)      base = nodes + (size_t)srcI[e0 + e] * 64;
        else if (c == 1) base = nodes + (size_t)dstI[e0 + e] * 64;
        else             base = efeat + (size_t)(e0 + e) * 128 + (c - 2) * 64;
#pragma unroll
        for (int gg = 0; gg < 2; gg++) {
          int g = q4 * 2 + gg;
          float4 v0 = ((const float4*)(base + g * 8))[0];
          float4 v1 = ((const float4*)(base + g * 8))[1];
          pxu[(4 * g + 0) * PXS + e] = make_uint2(__float_as_uint(v0.x), __float_as_uint(v1.x));
          pxu[(4 * g + 1) * PXS + e] = make_uint2(__float_as_uint(v0.y), __float_as_uint(v1.y));
          pxu[(4 * g + 2) * PXS + e] = make_uint2(__float_as_uint(v0.z), __float_as_uint(v1.z));
          pxu[(4 * g + 3) * PXS + e] = make_uint2(__float_as_uint(v0.w), __float_as_uint(v1.w));
        }
      }
      __syncthreads();

      const int prc = c * 32;   // W pair-row offset of this chunk
#pragma unroll
      for (int k8 = 0; k8 < 8; k8++) {
        const int prb = k8 * 4 + kl;
        uint2 a0[2], a1[2];
#pragma unroll
        for (int t = 0; t < 2; t++) {
          int m = mbase + t * 16 + r;
          a0[t] = pxu[prb * PXS + m];
          a1[t] = pxu[prb * PXS + m + 8];
        }
        uint2 bb[4];
#pragma unroll
        for (int u = 0; u < 4; u++) {
          int n = nbase + u * 8 + r;
          bb[u] = w1p[(prc + prb) * 128 + (n ^ (kl << 2))];
        }
#pragma unroll
        for (int t = 0; t < 2; t++)
#pragma unroll
          for (int u = 0; u < 4; u++)
            mma8(d1[t][u], a0[t].x, a1[t].x, a0[t].y, a1[t].y, bb[u].x, bb[u].y);
      }
    }

    // ---- h1 = silu(D1 + b1), raw fp32 bits ----
    unsigned h1f[2][4][4];
#pragma unroll
    for (int t = 0; t < 2; t++)
#pragma unroll
      for (int u = 0; u < 4; u++) {
        int n = nbase + u * 8 + 2 * kl;
        float ba = __ldg(&b1[n]), bb_ = __ldg(&b1[n + 1]);
        h1f[t][u][0] = __float_as_uint(silu_f(d1[t][u][0] + ba));
        h1f[t][u][1] = __float_as_uint(silu_f(d1[t][u][1] + bb_));
        h1f[t][u][2] = __float_as_uint(silu_f(d1[t][u][2] + ba));
        h1f[t][u][3] = __float_as_uint(silu_f(d1[t][u][3] + bb_));
      }

    // ================= GEMM2: D2 = H1[128,128] @ W2 =================
    float d2[2][4][4];
#pragma unroll
    for (int t = 0; t < 2; t++)
#pragma unroll
      for (int u = 0; u < 4; u++)
#pragma unroll
        for (int j = 0; j < 4; j++) d2[t][u][j] = 0.f;

#pragma unroll 1
    for (int c2 = 0; c2 < 2; c2++) {
      __syncthreads();   // px/sxu reads done
      if ((nj >> 1) == c2) {
        const int kloc0 = (nj & 1) * 32;
#pragma unroll
        for (int t = 0; t < 2; t++)
#pragma unroll
          for (int u = 0; u < 4; u++) {
            int m = mbase + t * 16 + r;
            int kk = kloc0 + u * 8 + 2 * kl;
            sxu[kk * HSTRIDE + m]           = h1f[t][u][0];
            sxu[(kk + 1) * HSTRIDE + m]     = h1f[t][u][1];
            sxu[kk * HSTRIDE + m + 8]       = h1f[t][u][2];
            sxu[(kk + 1) * HSTRIDE + m + 8] = h1f[t][u][3];
          }
      }
      __syncthreads();

      const int prc = c2 * 32;
#pragma unroll
      for (int k8 = 0; k8 < 8; k8++) {
        const int kb = k8 * 8;
        unsigned a[2][4];
#pragma unroll
        for (int t = 0; t < 2; t++) {
          int m = mbase + t * 16 + r;
          a[t][0] = sxu[(kb + kl) * HSTRIDE + m];
          a[t][1] = sxu[(kb + kl) * HSTRIDE + m + 8];
          a[t][2] = sxu[(kb + 4 + kl) * HSTRIDE + m];
          a[t][3] = sxu[(kb + 4 + kl) * HSTRIDE + m + 8];
        }
        uint2 bb[4];
#pragma unroll
        for (int u = 0; u < 4; u++) {
          int n = nbase + u * 8 + r;
          bb[u] = w2p[(prc + k8 * 4 + kl) * 128 + (n ^ (kl << 2))];
        }
#pragma unroll
        for (int t = 0; t < 2; t++)
#pragma unroll
          for (int u = 0; u < 4; u++)
            mma8(d2[t][u], a[t][0], a[t][1], a[t][2], a[t][3], bb[u].x, bb[u].y);
      }
    }

    // ================= epilogue: y = efeat + silu(D2+b2); LN =================
    float y[2][4][4];
    float s0[2], q0[2], s1[2], q1[2];
#pragma unroll
    for (int t = 0; t < 2; t++) { s0[t] = q0[t] = s1[t] = q1[t] = 0.f; }
#pragma unroll
    for (int t = 0; t < 2; t++) {
      int m = mbase + t * 16 + r;
#pragma unroll
      for (int u = 0; u < 4; u++) {
        int n = nbase + u * 8 + 2 * kl;
        float ba = __ldg(&b2[n]), bb_ = __ldg(&b2[n + 1]);
        float2 ef0 = *(const float2*)(efeat + (size_t)(e0 + m) * 128 + n);
        float2 ef1 = *(const float2*)(efeat + (size_t)(e0 + m + 8) * 128 + n);
        float v0 = ef0.x + silu_f(d2[t][u][0] + ba);
        float v1 = ef0.y + silu_f(d2[t][u][1] + bb_);
        float v2 = ef1.x + silu_f(d2[t][u][2] + ba);
        float v3 = ef1.y + silu_f(d2[t][u][3] + bb_);
        y[t][u][0] = v0; y[t][u][1] = v1; y[t][u][2] = v2; y[t][u][3] = v3;
        s0[t] += v0 + v1; q0[t] += v0 * v0 + v1 * v1;
        s1[t] += v2 + v3; q1[t] += v2 * v2 + v3 * v3;
      }
    }
#pragma unroll
    for (int t = 0; t < 2; t++) {
#pragma unroll
      for (int off = 1; off <= 2; off <<= 1) {
        s0[t] += __shfl_xor_sync(0xffffffffu, s0[t], off);
        q0[t] += __shfl_xor_sync(0xffffffffu, q0[t], off);
        s1[t] += __shfl_xor_sync(0xffffffffu, s1[t], off);
        q1[t] += __shfl_xor_sync(0xffffffffu, q1[t], off);
      }
    }
    __syncthreads();   // GEMM2 sxu reads complete
    float2* red = (float2*)sxu;   // [4 nj][128 m]
    if (kl == 0) {
#pragma unroll
      for (int t = 0; t < 2; t++) {
        int m = mbase + t * 16 + r;
        red[nj * 128 + m]     = make_float2(s0[t], q0[t]);
        red[nj * 128 + m + 8] = make_float2(s1[t], q1[t]);
      }
    }
    __syncthreads();
#pragma unroll
    for (int t = 0; t < 2; t++) {
      int m = mbase + t * 16 + r;
      float S0 = 0.f, Q0 = 0.f, S1 = 0.f, Q1 = 0.f;
#pragma unroll
      for (int qd = 0; qd < 4; qd++) {
        float2 v = red[qd * 128 + m];     S0 += v.x; Q0 += v.y;
        float2 w = red[qd * 128 + m + 8]; S1 += w.x; Q1 += w.y;
      }
      float mean0 = S0 * 0.0078125f;
      float var0  = Q0 * 0.0078125f - mean0 * mean0;
      float rs0   = rsqrtf(var0 + 1e-5f);
      float mean1 = S1 * 0.0078125f;
      float var1  = Q1 * 0.0078125f - mean1 * mean1;
      float rs1   = rsqrtf(var1 + 1e-5f);
#pragma unroll
      for (int u = 0; u < 4; u++) {
        int n = nbase + u * 8 + 2 * kl;
        float g0 = __ldg(&gamma[n]), g1 = __ldg(&gamma[n + 1]);
        float t0 = __ldg(&beta[n]),  t1 = __ldg(&beta[n + 1]);
        float2 o0, o1;
        o0.x = (y[t][u][0] - mean0) * rs0 * g0 + t0;
        o0.y = (y[t][u][1] - mean0) * rs0 * g1 + t1;
        o1.x = (y[t][u][2] - mean1) * rs1 * g0 + t0;
        o1.y = (y[t][u][3] - mean1) * rs1 * g1 + t1;
        *(float2*)(out + (size_t)(e0 + m) * 128 + n)     = o0;
        *(float2*)(out + (size_t)(e0 + m + 8) * 128 + n) = o1;
      }
    }
    // next tile's first __syncthreads orders sxu/red reuse
  }
}

extern "C" void kernel_launch(void* const* d_in, const int* in_sizes, int n_in,
                              void* d_out, int out_size) {
  const float* nodes = (const float*)d_in[0];
  const float* efeat = (const float*)d_in[1];
  const int*   srcI  = (const int*)d_in[2];
  const int*   dstI  = (const int*)d_in[3];
  const float* W1    = (const float*)d_in[4];
  const float* b1    = (const float*)d_in[5];
  const float* W2    = (const float*)d_in[6];
  const float* b2    = (const float*)d_in[7];
  const float* gamma = (const float*)d_in[8];
  const float* beta  = (const float*)d_in[9];
  float* out = (float*)d_out;

  cudaFuncSetAttribute(edge_update_mma4,
                       cudaFuncAttributeMaxDynamicSharedMemorySize, SMEM_BYTES);
  int sms = 148;
  cudaDeviceGetAttribute(&sms, cudaDevAttrMultiProcessorCount, 0);
  if (sms < 1) sms = 148;

  edge_update_mma4<<<sms, THREADS, SMEM_BYTES>>>(
      nodes, efeat, srcI, dstI, W1, b1, W2, b2, gamma, beta, out);
}